// round 8
// baseline (speedup 1.0000x reference)
#include <cuda_runtime.h>
#include <cuda_bf16.h>
#include <math.h>
#include <stdint.h>

// Problem constants
#define D_DIM 1024
#define B_DIM 32
#define NBLK  128      // 4 groups x 32 blocks, 1 CTA/SM, all co-resident
#define NGROUP 4
#define GSZ    32      // blocks per group
#define BSUB   8       // batches per group

// -------------------- device scratch (no cudaMalloc allowed) --------------------
__device__ float g_scale;
__device__ float g_state[NGROUP][2][D_DIM * BSUB]; // per-group state, [d][b_sub], double-buffered
__device__ unsigned g_cnt[NGROUP * 32];            // per-group barrier counters (128B apart)
__device__ volatile unsigned g_genv[NGROUP * 32];  // per-group barrier generations

// -------------------- block-wide sum over 1024 threads --------------------
__device__ __forceinline__ float block_sum1024(float v) {
    __shared__ float sr[32];
    __shared__ float res;
    #pragma unroll
    for (int o = 16; o; o >>= 1) v += __shfl_xor_sync(0xffffffffu, v, o);
    if ((threadIdx.x & 31) == 0) sr[threadIdx.x >> 5] = v;
    __syncthreads();
    if (threadIdx.x < 32) {
        float t = sr[threadIdx.x];
        #pragma unroll
        for (int o = 16; o; o >>= 1) t += __shfl_xor_sync(0xffffffffu, t, o);
        if (threadIdx.x == 0) res = t;
    }
    __syncthreads();
    float out = res;
    __syncthreads();
    return out;
}

// -------------------- 1) spectral norm power iteration --------------------
__global__ void spectral_kernel(const float* __restrict__ Wh,
                                const float* __restrict__ u0) {
    __shared__ float su[D_DIM];
    __shared__ float sv[D_DIM];
    __shared__ float sraw[D_DIM];
    const int tid  = threadIdx.x;
    const int w    = tid >> 5;
    const int lane = tid & 31;

    float x0 = u0[tid];
    float n0 = sqrtf(block_sum1024(x0 * x0));
    su[tid] = x0 / n0;
    __syncthreads();

    for (int it = 0; it < 3; it++) {
        {   // v = W^T u
            float a = 0.f;
            const float* col = Wh + tid;
            #pragma unroll 4
            for (int i = 0; i < D_DIM; i++)
                a = fmaf(col[(size_t)i * D_DIM], su[i], a);
            float nrm = sqrtf(block_sum1024(a * a));
            sv[tid] = a / (nrm + 1e-8f);
            __syncthreads();
        }
        {   // u_raw = W v
            for (int s = 0; s < 32; s++) {
                int r = w * 32 + s;
                const float* row = Wh + (size_t)r * D_DIM;
                float a = 0.f;
                #pragma unroll 4
                for (int k = lane; k < D_DIM; k += 32)
                    a = fmaf(row[k], sv[k], a);
                #pragma unroll
                for (int o = 16; o; o >>= 1) a += __shfl_xor_sync(0xffffffffu, a, o);
                if (lane == 0) sraw[r] = a;
            }
            __syncthreads();
            float rv  = sraw[tid];
            float nrm = sqrtf(block_sum1024(rv * rv));
            su[tid] = rv / (nrm + 1e-8f);
            __syncthreads();
        }
    }
    float sg = block_sum1024(su[tid] * sraw[tid]);
    if (tid == 0) g_scale = 0.99f / (fabsf(sg) + 1e-8f);
}

// -------------------- 2) prep: state init + h[0] copy --------------------
__global__ void prep_kernel(const float* __restrict__ h0,
                            float* __restrict__ hout0) {
    int i = blockIdx.x * blockDim.x + threadIdx.x;
    if (i < B_DIM * D_DIM) {
        int b = i >> 10;
        int d = i & (D_DIM - 1);
        g_state[b >> 3][0][d * BSUB + (b & 7)] = h0[i];
        hout0[i] = h0[i];
    }
}

// -------------------- 3) split-tf32 tensor-core GEMM: C[m][e] = sum_d X[m][d] W[e][d] ----
#define GS 36

__device__ __forceinline__ void tf32_split(float v, float& h, float& l) {
    uint32_t hb; asm("cvt.rna.tf32.f32 %0, %1;" : "=r"(hb) : "f"(v));
    float hf = __uint_as_float(hb);
    float lv = v - hf;
    uint32_t lb; asm("cvt.rna.tf32.f32 %0, %1;" : "=r"(lb) : "f"(lv));
    h = hf; l = __uint_as_float(lb);
}

__device__ __forceinline__ void mma_tf32(float* c, const uint32_t* a, const uint32_t* b) {
    asm volatile(
        "mma.sync.aligned.m16n8k8.row.col.f32.tf32.tf32.f32 "
        "{%0,%1,%2,%3}, {%4,%5,%6,%7}, {%8,%9}, {%0,%1,%2,%3};"
        : "+f"(c[0]), "+f"(c[1]), "+f"(c[2]), "+f"(c[3])
        : "r"(a[0]), "r"(a[1]), "r"(a[2]), "r"(a[3]), "r"(b[0]), "r"(b[1]));
}

__global__ __launch_bounds__(256, 1)
void gemm_tf32_kernel(const float* __restrict__ X,
                      const float* __restrict__ Wg,
                      float* __restrict__ C) {
    extern __shared__ float gsm[];
    float* Xh = gsm;
    float* Xl = Xh + 128 * GS;
    float* Wh = Xl + 128 * GS;
    float* Wl = Wh + 128 * GS;

    const int tid  = threadIdx.x;
    const int bn   = blockIdx.x * 128;
    const int bm   = blockIdx.y * 128;
    const int wid  = tid >> 5, lane = tid & 31;
    const int wm   = wid >> 2;
    const int wn   = wid & 3;
    const int gid  = lane >> 2, tig = lane & 3;

    float c[4][4][4];
    #pragma unroll
    for (int mt = 0; mt < 4; mt++)
        #pragma unroll
        for (int nt = 0; nt < 4; nt++)
            #pragma unroll
            for (int r = 0; r < 4; r++) c[mt][nt][r] = 0.f;

    const int sr = tid >> 3;
    const int sc = (tid & 7) * 4;

    for (int k0 = 0; k0 < D_DIM; k0 += 32) {
        __syncthreads();
        #pragma unroll
        for (int j = 0; j < 4; j++) {
            int row = sr + j * 32;
            float4 xv = *(const float4*)&X[(size_t)(bm + row) * D_DIM + k0 + sc];
            float4 wv = *(const float4*)&Wg[(size_t)(bn + row) * D_DIM + k0 + sc];
            float h, l;
            tf32_split(xv.x, h, l); Xh[row*GS+sc+0]=h; Xl[row*GS+sc+0]=l;
            tf32_split(xv.y, h, l); Xh[row*GS+sc+1]=h; Xl[row*GS+sc+1]=l;
            tf32_split(xv.z, h, l); Xh[row*GS+sc+2]=h; Xl[row*GS+sc+2]=l;
            tf32_split(xv.w, h, l); Xh[row*GS+sc+3]=h; Xl[row*GS+sc+3]=l;
            tf32_split(wv.x, h, l); Wh[row*GS+sc+0]=h; Wl[row*GS+sc+0]=l;
            tf32_split(wv.y, h, l); Wh[row*GS+sc+1]=h; Wl[row*GS+sc+1]=l;
            tf32_split(wv.z, h, l); Wh[row*GS+sc+2]=h; Wl[row*GS+sc+2]=l;
            tf32_split(wv.w, h, l); Wh[row*GS+sc+3]=h; Wl[row*GS+sc+3]=l;
        }
        __syncthreads();
        #pragma unroll
        for (int k8 = 0; k8 < 4; k8++) {
            const int kk = k8 * 8 + tig;
            uint32_t ah[4][4], al[4][4], bh[4][2], bl[4][2];
            #pragma unroll
            for (int mt = 0; mt < 4; mt++) {
                int r0 = wm * 64 + mt * 16 + gid;
                const float* p0 = &Xh[r0 * GS + kk];
                ah[mt][0] = __float_as_uint(p0[0]);
                ah[mt][1] = __float_as_uint(p0[8 * GS]);
                ah[mt][2] = __float_as_uint(p0[4]);
                ah[mt][3] = __float_as_uint(p0[8 * GS + 4]);
                const float* p1 = &Xl[r0 * GS + kk];
                al[mt][0] = __float_as_uint(p1[0]);
                al[mt][1] = __float_as_uint(p1[8 * GS]);
                al[mt][2] = __float_as_uint(p1[4]);
                al[mt][3] = __float_as_uint(p1[8 * GS + 4]);
            }
            #pragma unroll
            for (int nt = 0; nt < 4; nt++) {
                int c0n = wn * 32 + nt * 8 + gid;
                const float* p0 = &Wh[c0n * GS + kk];
                bh[nt][0] = __float_as_uint(p0[0]);
                bh[nt][1] = __float_as_uint(p0[4]);
                const float* p1 = &Wl[c0n * GS + kk];
                bl[nt][0] = __float_as_uint(p1[0]);
                bl[nt][1] = __float_as_uint(p1[4]);
            }
            #pragma unroll
            for (int mt = 0; mt < 4; mt++)
                #pragma unroll
                for (int nt = 0; nt < 4; nt++) {
                    mma_tf32(c[mt][nt], ah[mt], bh[nt]);
                    mma_tf32(c[mt][nt], ah[mt], bl[nt]);
                    mma_tf32(c[mt][nt], al[mt], bh[nt]);
                }
        }
    }
    #pragma unroll
    for (int mt = 0; mt < 4; mt++) {
        int row = bm + wm * 64 + mt * 16 + gid;
        #pragma unroll
        for (int nt = 0; nt < 4; nt++) {
            int col = bn + wn * 32 + nt * 8 + 2 * tig;
            *(float2*)&C[(size_t)row * D_DIM + col]       = make_float2(c[mt][nt][0], c[mt][nt][1]);
            *(float2*)&C[(size_t)(row + 8) * D_DIM + col] = make_float2(c[mt][nt][2], c[mt][nt][3]);
        }
    }
}

// -------------------- 4) persistent scan kernel (v4: 512 threads, private W, shfl reduce) ----
// Group g (32 blocks) owns batches [8g, 8g+8). Block owns 32 e's.
// 512 threads = 16 warps; warp w covers d-chunk [w*64, w*64+64).
// lane: eg = lane&3 (8 e's each), dsub = lane>>2 (d = w*64 + dsub + 8i, i<8).
// W scaled & private per thread in smem (stride 68 floats => conflict-free LDS.128).
// Thread tile 8e x 8b x 8d = 512 FMA. Warp shuffle butterfly over dsub (xor 16/8/4)
// collapses partials to per-warp tiles; cross-warp reduce = 16 conflict-free LDS.
#define SC_T 512
#define W_RS 68                 // per-thread W region stride (floats); 68 % 32 == 4
#define RED_W 288               // per-warp red row (8 b * 36)
#define SCAN_SMEM_FLOATS (SC_T * W_RS + 16 * RED_W + 64)

__global__ __launch_bounds__(SC_T, 1)
void scan_kernel(const float* __restrict__ Whmat,
                 float* __restrict__ wx_out,        // [T][B][D]: in = Wx, overwritten with out
                 float* __restrict__ hout,          // [T+1][B][D]
                 const float* __restrict__ bvec,
                 const float* __restrict__ bgvec,
                 int T) {
    extern __shared__ float sm[];
    float* wreg = sm;                        // SC_T * W_RS (per-thread private W)
    float* red  = wreg + SC_T * W_RS;        // 16 * RED_W
    float* bsm  = red + 16 * RED_W;          // 32
    float* bgsm = bsm + 32;                  // 32

    const int tid  = threadIdx.x;
    const int g    = blockIdx.x >> 5;        // group 0..3
    const int r    = blockIdx.x & 31;        // rank in group
    const int e0   = r * 32;
    const int b0   = g * BSUB;
    const int bar  = g * 32;

    const int w    = tid >> 5;               // warp 0..15
    const int lane = tid & 31;
    const int eg   = lane & 3;               // e-range eg*8..+8
    const int dsub = lane >> 2;              // 0..7

    // init: private scaled W, layout [i][e] in read order
    {
        const float s = g_scale;
        float* reg = wreg + tid * W_RS;
        #pragma unroll
        for (int i = 0; i < 8; i++)
            #pragma unroll
            for (int e = 0; e < 8; e++)
                reg[i * 8 + e] =
                    Whmat[(size_t)(e0 + eg * 8 + e) * D_DIM + (w * 64 + dsub + 8 * i)] * s;
    }
    if (tid < 32) { bsm[tid] = bvec[e0 + tid]; bgsm[tid] = bgvec[e0 + tid]; }
    __syncthreads();

    const int eL = tid & 31;                 // epilogue mapping (tid < 256)
    const int bO = tid >> 5;
    const float* wp = wreg + tid * W_RS;

    unsigned gen = g_genv[bar];
    int par = 0;

    for (int t = 0; t < T; t++) {
        // prefetch Wx for epilogue threads (overlaps FMA loop)
        size_t gidx = 0; float wxv = 0.f;
        if (tid < 256) {
            gidx = ((size_t)t * B_DIM + (b0 + bO)) * D_DIM + (e0 + eL);
            wxv = __ldcg(&wx_out[gidx]);
        }

        float acc[8][8];
        #pragma unroll
        for (int e = 0; e < 8; e++)
            #pragma unroll
            for (int b = 0; b < 8; b++) acc[e][b] = 0.f;

        const float4* hsrc = (const float4*)g_state[g][par];
        #pragma unroll
        for (int i = 0; i < 8; i++) {
            const int d = w * 64 + dsub + 8 * i;
            float4 h0v = __ldcg(hsrc + (size_t)d * 2);
            float4 h1v = __ldcg(hsrc + (size_t)d * 2 + 1);
            float4 w0v = *(const float4*)(wp + i * 8);
            float4 w1v = *(const float4*)(wp + i * 8 + 4);
            float wv[8] = {w0v.x, w0v.y, w0v.z, w0v.w, w1v.x, w1v.y, w1v.z, w1v.w};
            float hv[8] = {h0v.x, h0v.y, h0v.z, h0v.w, h1v.x, h1v.y, h1v.z, h1v.w};
            #pragma unroll
            for (int e = 0; e < 8; e++)
                #pragma unroll
                for (int b = 0; b < 8; b++)
                    acc[e][b] = fmaf(wv[e], hv[b], acc[e][b]);
        }

        // warp butterfly over dsub: after 3 rounds, thread (eg,dsub) holds
        // sum over all dsub-lanes of acc[8e][b = dsub]
        float a2[8][4];
        {
            const bool hi = (dsub & 4) != 0;
            #pragma unroll
            for (int e = 0; e < 8; e++)
                #pragma unroll
                for (int k = 0; k < 4; k++) {
                    float give = hi ? acc[e][k] : acc[e][k + 4];
                    float keep = hi ? acc[e][k + 4] : acc[e][k];
                    a2[e][k] = keep + __shfl_xor_sync(0xffffffffu, give, 16);
                }
        }
        float a3[8][2];
        {
            const bool hi = (dsub & 2) != 0;
            #pragma unroll
            for (int e = 0; e < 8; e++)
                #pragma unroll
                for (int k = 0; k < 2; k++) {
                    float give = hi ? a2[e][k] : a2[e][k + 2];
                    float keep = hi ? a2[e][k + 2] : a2[e][k];
                    a3[e][k] = keep + __shfl_xor_sync(0xffffffffu, give, 8);
                }
        }
        float a4[8];
        {
            const bool hi = (dsub & 1) != 0;
            #pragma unroll
            for (int e = 0; e < 8; e++) {
                float give = hi ? a3[e][0] : a3[e][1];
                float keep = hi ? a3[e][1] : a3[e][0];
                a4[e] = keep + __shfl_xor_sync(0xffffffffu, give, 4);
            }
        }

        // per-warp tile -> red[w][dsub(b)*36 + eg*8 + e]  (conflict-free STS.128)
        {
            float* dst = red + w * RED_W + dsub * 36 + eg * 8;
            *(float4*)dst       = make_float4(a4[0], a4[1], a4[2], a4[3]);
            *(float4*)(dst + 4) = make_float4(a4[4], a4[5], a4[6], a4[7]);
        }
        __syncthreads();

        // cross-warp reduce (16 partials) + epilogue, tid<256: one (e,b) each
        if (tid < 256) {
            const int off = bO * 36 + eL;
            float s0 = 0.f, s1 = 0.f, s2 = 0.f, s3 = 0.f;
            #pragma unroll
            for (int q = 0; q < 16; q += 4) {
                s0 += red[(q + 0) * RED_W + off];
                s1 += red[(q + 1) * RED_W + off];
                s2 += red[(q + 2) * RED_W + off];
                s3 += red[(q + 3) * RED_W + off];
            }
            const float dot = (s0 + s1) + (s2 + s3);
            const float raw = wxv + dot + bsm[eL];
            const float ex  = __expf(2.f * raw);
            const float hn  = 1.f - 2.f / (ex + 1.f);           // tanh(raw)
            const float gg  = wxv + hn + bgsm[eL];
            const float ov  = hn * gg / (1.f + __expf(-gg));    // hn * silu(gg)
            wx_out[gidx] = ov;
            hout[((size_t)(t + 1) * B_DIM + (b0 + bO)) * D_DIM + (e0 + eL)] = hn;
            g_state[g][par ^ 1][(e0 + eL) * BSUB + bO] = hn;    // direct state store
        }
        __syncthreads();

        // per-group barrier
        if (tid == 0) {
            __threadfence();
            if (atomicAdd(&g_cnt[bar], 1u) == GSZ - 1) {
                atomicExch(&g_cnt[bar], 0u);
                __threadfence();
                g_genv[bar] = gen + 1;
            } else {
                while (g_genv[bar] == gen) { }
            }
            gen = gen + 1;
        }
        __syncthreads();
        par ^= 1;
    }
}

// -------------------- launcher --------------------
extern "C" void kernel_launch(void* const* d_in, const int* in_sizes, int n_in,
                              void* d_out, int out_size) {
    const float* x      = (const float*)d_in[0];
    // d_in[1] = z (unused, gate_mode 0)
    const float* h0     = (const float*)d_in[2];
    const float* W_x    = (const float*)d_in[3];
    const float* W_h    = (const float*)d_in[4];
    const float* bvec   = (const float*)d_in[5];
    const float* bgvec  = (const float*)d_in[6];
    const float* u0     = (const float*)d_in[7];

    const int T = in_sizes[0] / (B_DIM * D_DIM);   // 2048
    const int M = T * B_DIM;                       // 65536

    float* out_region = (float*)d_out;                               // [T][B][D]
    float* h_region   = (float*)d_out + (size_t)T * B_DIM * D_DIM;   // [T+1][B][D]

    const size_t scan_smem = SCAN_SMEM_FLOATS * sizeof(float);       // ~158 KB
    const size_t gemm_smem = 4 * 128 * GS * sizeof(float);           // 73728 B

    static bool attrs_set = false;
    if (!attrs_set) {
        cudaFuncSetAttribute(scan_kernel,
                             cudaFuncAttributeMaxDynamicSharedMemorySize, (int)scan_smem);
        cudaFuncSetAttribute(gemm_tf32_kernel,
                             cudaFuncAttributeMaxDynamicSharedMemorySize, (int)gemm_smem);
        attrs_set = true;
    }

    spectral_kernel<<<1, 1024>>>(W_h, u0);
    prep_kernel<<<(B_DIM * D_DIM + 255) / 256, 256>>>(h0, h_region);

    {
        dim3 grid(D_DIM / 128, M / 128);
        gemm_tf32_kernel<<<grid, 256, gemm_smem>>>(x, W_x, out_region);
    }

    scan_kernel<<<NBLK, SC_T, scan_smem>>>(W_h, out_region, h_region, bvec, bgvec, T);
}

// round 10
// speedup vs baseline: 1.4575x; 1.4575x over previous
#include <cuda_runtime.h>
#include <cuda_bf16.h>
#include <math.h>
#include <stdint.h>

// Problem constants
#define D_DIM 1024
#define B_DIM 32
#define NBLK  128      // 4 groups x 32 blocks, 1 CTA/SM, all co-resident
#define NGROUP 4
#define GSZ    32      // blocks per group
#define BSUB   8       // batches per group

// -------------------- device scratch (no cudaMalloc allowed) --------------------
__device__ float g_scale;
__device__ float g_Wsc[D_DIM * D_DIM];             // W_h * scale, row-major [e][d]
__device__ float g_WxHi[D_DIM * D_DIM];            // W_x tf32 hi split
__device__ float g_WxLo[D_DIM * D_DIM];            // W_x tf32 lo split
__device__ float g_state[NGROUP][2][D_DIM * BSUB]; // per-group state, [d][b_sub], double-buffered
__device__ unsigned g_cnt[NGROUP * 32];            // per-group barrier counters
__device__ volatile unsigned g_genv[NGROUP * 32];  // per-group barrier generations

// -------------------- block-wide sum over 1024 threads --------------------
__device__ __forceinline__ float block_sum1024(float v) {
    __shared__ float sr[32];
    __shared__ float res;
    #pragma unroll
    for (int o = 16; o; o >>= 1) v += __shfl_xor_sync(0xffffffffu, v, o);
    if ((threadIdx.x & 31) == 0) sr[threadIdx.x >> 5] = v;
    __syncthreads();
    if (threadIdx.x < 32) {
        float t = sr[threadIdx.x];
        #pragma unroll
        for (int o = 16; o; o >>= 1) t += __shfl_xor_sync(0xffffffffu, t, o);
        if (threadIdx.x == 0) res = t;
    }
    __syncthreads();
    float out = res;
    __syncthreads();
    return out;
}

// -------------------- 1) spectral norm power iteration --------------------
__global__ void spectral_kernel(const float* __restrict__ Wh,
                                const float* __restrict__ u0) {
    __shared__ float su[D_DIM];
    __shared__ float sv[D_DIM];
    __shared__ float sraw[D_DIM];
    const int tid  = threadIdx.x;
    const int w    = tid >> 5;
    const int lane = tid & 31;

    float x0 = u0[tid];
    float n0 = sqrtf(block_sum1024(x0 * x0));
    su[tid] = x0 / n0;
    __syncthreads();

    for (int it = 0; it < 3; it++) {
        {   // v = W^T u
            float a = 0.f;
            const float* col = Wh + tid;
            #pragma unroll 4
            for (int i = 0; i < D_DIM; i++)
                a = fmaf(col[(size_t)i * D_DIM], su[i], a);
            float nrm = sqrtf(block_sum1024(a * a));
            sv[tid] = a / (nrm + 1e-8f);
            __syncthreads();
        }
        {   // u_raw = W v
            for (int s = 0; s < 32; s++) {
                int r = w * 32 + s;
                const float* row = Wh + (size_t)r * D_DIM;
                float a = 0.f;
                #pragma unroll 4
                for (int k = lane; k < D_DIM; k += 32)
                    a = fmaf(row[k], sv[k], a);
                #pragma unroll
                for (int o = 16; o; o >>= 1) a += __shfl_xor_sync(0xffffffffu, a, o);
                if (lane == 0) sraw[r] = a;
            }
            __syncthreads();
            float rv  = sraw[tid];
            float nrm = sqrtf(block_sum1024(rv * rv));
            su[tid] = rv / (nrm + 1e-8f);
            __syncthreads();
        }
    }
    float sg = block_sum1024(su[tid] * sraw[tid]);
    if (tid == 0) g_scale = 0.99f / (fabsf(sg) + 1e-8f);
}

// -------------------- tf32 split helpers --------------------
__device__ __forceinline__ void tf32_split(float v, float& h, float& l) {
    uint32_t hb; asm("cvt.rna.tf32.f32 %0, %1;" : "=r"(hb) : "f"(v));
    float hf = __uint_as_float(hb);
    float lv = v - hf;
    uint32_t lb; asm("cvt.rna.tf32.f32 %0, %1;" : "=r"(lb) : "f"(lv));
    h = hf; l = __uint_as_float(lb);
}

// -------------------- 2a) split W_x once (reused by all 512 m-tiles) --------------------
__global__ void wsplit_kernel(const float* __restrict__ Wx) {
    int i = blockIdx.x * blockDim.x + threadIdx.x;
    if (i < D_DIM * D_DIM) {
        float h, l;
        tf32_split(Wx[i], h, l);
        g_WxHi[i] = h;
        g_WxLo[i] = l;
    }
}

// -------------------- 2b) prep: scale W_h, transpose h0, copy h0 to output ----------
__global__ void prep_kernel(const float* __restrict__ Wh,
                            const float* __restrict__ h0,
                            float* __restrict__ hout0) {
    const float s = g_scale;
    int i = blockIdx.x * blockDim.x + threadIdx.x;
    if (i < D_DIM * D_DIM) g_Wsc[i] = Wh[i] * s;
    if (i < B_DIM * D_DIM) {
        int b = i >> 10;
        int d = i & (D_DIM - 1);
        g_state[b >> 3][0][d * BSUB + (b & 7)] = h0[i];
        hout0[i] = h0[i];
    }
}

// -------------------- 3) split-tf32 tensor-core GEMM: C[m][e] = sum_d X[m][d] W[e][d] ----
// BM=BN=128, BK=32, 256 threads, 8 warps (2 m x 4 n), warp tile 64x32.
// W hi/lo pre-split, read from __device__ globals INSIDE the kernel (no host symbol UB).
// 2 CTAs/SM for latency hiding.
#define GS 36

__device__ __forceinline__ void mma_tf32(float* c, const uint32_t* a, const uint32_t* b) {
    asm volatile(
        "mma.sync.aligned.m16n8k8.row.col.f32.tf32.tf32.f32 "
        "{%0,%1,%2,%3}, {%4,%5,%6,%7}, {%8,%9}, {%0,%1,%2,%3};"
        : "+f"(c[0]), "+f"(c[1]), "+f"(c[2]), "+f"(c[3])
        : "r"(a[0]), "r"(a[1]), "r"(a[2]), "r"(a[3]), "r"(b[0]), "r"(b[1]));
}

__global__ __launch_bounds__(256, 2)
void gemm_tf32_kernel(const float* __restrict__ X,
                      float* __restrict__ C) {
    extern __shared__ float gsm[];
    float* Xh = gsm;
    float* Xl = Xh + 128 * GS;
    float* Wh = Xl + 128 * GS;
    float* Wl = Wh + 128 * GS;

    const float* __restrict__ WHi = g_WxHi;   // device globals, valid addresses in-kernel
    const float* __restrict__ WLo = g_WxLo;

    const int tid  = threadIdx.x;
    const int bn   = blockIdx.x * 128;
    const int bm   = blockIdx.y * 128;
    const int wid  = tid >> 5, lane = tid & 31;
    const int wm   = wid >> 2;
    const int wn   = wid & 3;
    const int gid  = lane >> 2, tig = lane & 3;

    float c[4][4][4];
    #pragma unroll
    for (int mt = 0; mt < 4; mt++)
        #pragma unroll
        for (int nt = 0; nt < 4; nt++)
            #pragma unroll
            for (int r = 0; r < 4; r++) c[mt][nt][r] = 0.f;

    const int sr = tid >> 3;
    const int sc = (tid & 7) * 4;

    for (int k0 = 0; k0 < D_DIM; k0 += 32) {
        __syncthreads();
        #pragma unroll
        for (int j = 0; j < 4; j++) {
            int row = sr + j * 32;
            float4 xv  = *(const float4*)&X[(size_t)(bm + row) * D_DIM + k0 + sc];
            float4 wvh = *(const float4*)&WHi[(size_t)(bn + row) * D_DIM + k0 + sc];
            float4 wvl = *(const float4*)&WLo[(size_t)(bn + row) * D_DIM + k0 + sc];
            float h, l;
            tf32_split(xv.x, h, l); Xh[row*GS+sc+0]=h; Xl[row*GS+sc+0]=l;
            tf32_split(xv.y, h, l); Xh[row*GS+sc+1]=h; Xl[row*GS+sc+1]=l;
            tf32_split(xv.z, h, l); Xh[row*GS+sc+2]=h; Xl[row*GS+sc+2]=l;
            tf32_split(xv.w, h, l); Xh[row*GS+sc+3]=h; Xl[row*GS+sc+3]=l;
            *(float4*)&Wh[row*GS+sc] = wvh;
            *(float4*)&Wl[row*GS+sc] = wvl;
        }
        __syncthreads();
        #pragma unroll
        for (int k8 = 0; k8 < 4; k8++) {
            const int kk = k8 * 8 + tig;
            uint32_t ah[4][4], al[4][4], bh[4][2], bl[4][2];
            #pragma unroll
            for (int mt = 0; mt < 4; mt++) {
                int r0 = wm * 64 + mt * 16 + gid;
                const float* p0 = &Xh[r0 * GS + kk];
                ah[mt][0] = __float_as_uint(p0[0]);
                ah[mt][1] = __float_as_uint(p0[8 * GS]);
                ah[mt][2] = __float_as_uint(p0[4]);
                ah[mt][3] = __float_as_uint(p0[8 * GS + 4]);
                const float* p1 = &Xl[r0 * GS + kk];
                al[mt][0] = __float_as_uint(p1[0]);
                al[mt][1] = __float_as_uint(p1[8 * GS]);
                al[mt][2] = __float_as_uint(p1[4]);
                al[mt][3] = __float_as_uint(p1[8 * GS + 4]);
            }
            #pragma unroll
            for (int nt = 0; nt < 4; nt++) {
                int c0n = wn * 32 + nt * 8 + gid;
                const float* p0 = &Wh[c0n * GS + kk];
                bh[nt][0] = __float_as_uint(p0[0]);
                bh[nt][1] = __float_as_uint(p0[4]);
                const float* p1 = &Wl[c0n * GS + kk];
                bl[nt][0] = __float_as_uint(p1[0]);
                bl[nt][1] = __float_as_uint(p1[4]);
            }
            #pragma unroll
            for (int mt = 0; mt < 4; mt++)
                #pragma unroll
                for (int nt = 0; nt < 4; nt++) {
                    mma_tf32(c[mt][nt], ah[mt], bh[nt]);
                    mma_tf32(c[mt][nt], ah[mt], bl[nt]);
                    mma_tf32(c[mt][nt], al[mt], bh[nt]);
                }
        }
    }
    #pragma unroll
    for (int mt = 0; mt < 4; mt++) {
        int row = bm + wm * 64 + mt * 16 + gid;
        #pragma unroll
        for (int nt = 0; nt < 4; nt++) {
            int col = bn + wn * 32 + nt * 8 + 2 * tig;
            *(float2*)&C[(size_t)row * D_DIM + col]       = make_float2(c[mt][nt][0], c[mt][nt][1]);
            *(float2*)&C[(size_t)(row + 8) * D_DIM + col] = make_float2(c[mt][nt][2], c[mt][nt][3]);
        }
    }
}

// -------------------- 4) persistent scan kernel (R6, known-good 9.56ms) ----------
#define W_STRIDE 36
#define RED_STRIDE 68
#define SCAN_SMEM_FLOATS (D_DIM * W_STRIDE + 256 * RED_STRIDE + 32 * 9 + 32 + 32)

__global__ __launch_bounds__(256, 1)
void scan_kernel(float* __restrict__ wx_out,        // [T][B][D]: in = Wx, overwritten with out
                 float* __restrict__ hout,          // [T+1][B][D]
                 const float* __restrict__ bvec,
                 const float* __restrict__ bgvec,
                 int T) {
    extern __shared__ float sm[];
    float* wT    = sm;                               // [d][W_STRIDE], e in slots 0..31
    float* red   = wT + D_DIM * W_STRIDE;            // [256][RED_STRIDE]
    float* hn_sm = red + 256 * RED_STRIDE;           // 32*9
    float* bsm   = hn_sm + 32 * 9;                   // 32
    float* bgsm  = bsm + 32;                         // 32

    const int tid = threadIdx.x;
    const int g   = blockIdx.x >> 5;     // group 0..3
    const int r   = blockIdx.x & 31;     // rank in group
    const int e0  = r * 32;
    const int b0  = g * BSUB;
    const int bar = g * 32;              // barrier slot

    // W slice transposed into smem: wT[d*36 + e] = Wsc[e0+e][d]
    for (int i = tid; i < 32 * D_DIM; i += 256) {
        int e = i >> 10;
        int d = i & (D_DIM - 1);
        wT[d * W_STRIDE + e] = g_Wsc[(size_t)(e0 + e) * D_DIM + d];
    }
    if (tid < 32) { bsm[tid] = bvec[e0 + tid]; bgsm[tid] = bgvec[e0 + tid]; }
    __syncthreads();

    const int w    = tid >> 5;
    const int lane = tid & 31;
    const int eg   = lane >> 3;          // 0..3 : which 8 e's
    const int dsub = lane & 7;           // 0..7
    const int d0   = w * 128;
    const int pcol = ((w * 8 + dsub) + 8 * eg) & 63;   // rotated partial column
    const int eL   = tid & 31;           // epilogue: e (coalesced wx/hout)
    const int bO   = tid >> 5;           // epilogue: batch within group (0..7)
    const int rrow = (bO * 32 + eL) * RED_STRIDE;
    const int rrot = (eL >> 3) * 8;      // reduce-side rotation

    unsigned gen = g_genv[bar];
    int par = 0;

    for (int t = 0; t < T; t++) {
        // prefetch this thread's Wx element (L2 latency overlaps FMA loop)
        const size_t gidx = ((size_t)t * B_DIM + (b0 + bO)) * D_DIM + (e0 + eL);
        const float wxv = __ldcg(&wx_out[gidx]);

        float acc[8][8];
        #pragma unroll
        for (int e = 0; e < 8; e++)
            #pragma unroll
            for (int b = 0; b < 8; b++) acc[e][b] = 0.f;

        const float4* hsrc = (const float4*)g_state[g][par];
        #pragma unroll 4
        for (int i = 0; i < 16; i++) {
            const int d = d0 + dsub + 8 * i;
            float4 h0v = __ldcg(hsrc + (size_t)d * 2);
            float4 h1v = __ldcg(hsrc + (size_t)d * 2 + 1);
            const float* wp = wT + d * W_STRIDE + eg * 8;
            float4 w0v = *(const float4*)wp;
            float4 w1v = *(const float4*)(wp + 4);
            float wv[8] = {w0v.x, w0v.y, w0v.z, w0v.w, w1v.x, w1v.y, w1v.z, w1v.w};
            float hv[8] = {h0v.x, h0v.y, h0v.z, h0v.w, h1v.x, h1v.y, h1v.z, h1v.w};
            #pragma unroll
            for (int e = 0; e < 8; e++)
                #pragma unroll
                for (int b = 0; b < 8; b++)
                    acc[e][b] = fmaf(wv[e], hv[b], acc[e][b]);
        }

        // partials -> red[o][pcol], o = b*32 + eg*8 + ei  (conflict-free scalar STS)
        #pragma unroll
        for (int ei = 0; ei < 8; ei++)
            #pragma unroll
            for (int b = 0; b < 8; b++)
                red[(b * 32 + eg * 8 + ei) * RED_STRIDE + pcol] = acc[ei][b];
        __syncthreads();

        // reduce 64 partials with conflict-free float4 loads + epilogue
        {
            float s0 = 0.f, s1 = 0.f, s2 = 0.f, s3 = 0.f;
            #pragma unroll
            for (int q = 0; q < 16; q += 4) {
                float4 v0 = *(const float4*)&red[rrow + ((4 * (q + 0) + rrot) & 63)];
                float4 v1 = *(const float4*)&red[rrow + ((4 * (q + 1) + rrot) & 63)];
                float4 v2 = *(const float4*)&red[rrow + ((4 * (q + 2) + rrot) & 63)];
                float4 v3 = *(const float4*)&red[rrow + ((4 * (q + 3) + rrot) & 63)];
                s0 += v0.x + v0.y + v0.z + v0.w;
                s1 += v1.x + v1.y + v1.z + v1.w;
                s2 += v2.x + v2.y + v2.z + v2.w;
                s3 += v3.x + v3.y + v3.z + v3.w;
            }
            const float dot = (s0 + s1) + (s2 + s3);
            const float raw = wxv + dot + bsm[eL];
            const float ex  = __expf(2.f * raw);
            const float hn  = 1.f - 2.f / (ex + 1.f);           // tanh(raw)
            const float gg  = wxv + hn + bgsm[eL];
            const float ov  = hn * gg / (1.f + __expf(-gg));    // hn * silu(gg)
            wx_out[gidx] = ov;
            hout[((size_t)(t + 1) * B_DIM + (b0 + bO)) * D_DIM + (e0 + eL)] = hn;
            hn_sm[eL * 9 + bO] = hn;                             // conflict-free
        }
        __syncthreads();

        // publish next state: contiguous coalesced 1KB; conflict-free hn_sm reads
        g_state[g][par ^ 1][e0 * BSUB + tid] = hn_sm[(tid >> 3) * 9 + (tid & 7)];
        __syncthreads();

        // per-group barrier
        if (tid == 0) {
            __threadfence();
            if (atomicAdd(&g_cnt[bar], 1u) == GSZ - 1) {
                atomicExch(&g_cnt[bar], 0u);
                __threadfence();
                g_genv[bar] = gen + 1;
            } else {
                while (g_genv[bar] == gen) { }
            }
            gen = gen + 1;
        }
        __syncthreads();
        par ^= 1;
    }
}

// -------------------- launcher --------------------
extern "C" void kernel_launch(void* const* d_in, const int* in_sizes, int n_in,
                              void* d_out, int out_size) {
    const float* x      = (const float*)d_in[0];
    // d_in[1] = z (unused, gate_mode 0)
    const float* h0     = (const float*)d_in[2];
    const float* W_x    = (const float*)d_in[3];
    const float* W_h    = (const float*)d_in[4];
    const float* bvec   = (const float*)d_in[5];
    const float* bgvec  = (const float*)d_in[6];
    const float* u0     = (const float*)d_in[7];

    const int T = in_sizes[0] / (B_DIM * D_DIM);   // 2048
    const int M = T * B_DIM;                       // 65536

    float* out_region = (float*)d_out;                               // [T][B][D]
    float* h_region   = (float*)d_out + (size_t)T * B_DIM * D_DIM;   // [T+1][B][D]

    const size_t scan_smem = SCAN_SMEM_FLOATS * sizeof(float);       // ~218.6 KB
    const size_t gemm_smem = 4 * 128 * GS * sizeof(float);           // 73728 B

    static bool attrs_set = false;
    if (!attrs_set) {
        cudaFuncSetAttribute(scan_kernel,
                             cudaFuncAttributeMaxDynamicSharedMemorySize, (int)scan_smem);
        cudaFuncSetAttribute(gemm_tf32_kernel,
                             cudaFuncAttributeMaxDynamicSharedMemorySize, (int)gemm_smem);
        attrs_set = true;
    }

    wsplit_kernel<<<(D_DIM * D_DIM + 255) / 256, 256>>>(W_x);
    spectral_kernel<<<1, 1024>>>(W_h, u0);
    prep_kernel<<<(D_DIM * D_DIM + 255) / 256, 256>>>(W_h, h0, h_region);

    {
        dim3 grid(D_DIM / 128, M / 128);
        gemm_tf32_kernel<<<grid, 256, gemm_smem>>>(x, out_region);
    }

    scan_kernel<<<NBLK, 256, scan_smem>>>(out_region, h_region, bvec, bgvec, T);
}

// round 11
// speedup vs baseline: 1.9584x; 1.3437x over previous
#include <cuda_runtime.h>
#include <cuda_bf16.h>
#include <math.h>
#include <stdint.h>

// Problem constants
#define D_DIM 1024
#define B_DIM 32
#define NBLK  128      // 4 groups x 32 blocks, 1 CTA/SM, all co-resident
#define NGROUP 4
#define GSZ    32      // blocks per group
#define BSUB   8       // batches per group

// -------------------- device scratch (no cudaMalloc allowed) --------------------
__device__ float g_scale;
__device__ float g_WxHi[D_DIM * D_DIM];            // W_x tf32 hi split
__device__ float g_WxLo[D_DIM * D_DIM];            // W_x tf32 lo split
// packed bf16 recurrent state, mma-B-fragment layout:
// [group][parity][sblk(64)][tig(4)][gid(8)] -> uint4 (bhi0,bhi1,blo0,blo1)
__device__ uint32_t g_spack[NGROUP][2][64 * 4 * 8 * 4];
__device__ unsigned g_cnt[NGROUP * 32];            // per-group barrier counters
__device__ volatile unsigned g_genv[NGROUP * 32];  // per-group barrier generations

// -------------------- block-wide sum over 1024 threads --------------------
__device__ __forceinline__ float block_sum1024(float v) {
    __shared__ float sr[32];
    __shared__ float res;
    #pragma unroll
    for (int o = 16; o; o >>= 1) v += __shfl_xor_sync(0xffffffffu, v, o);
    if ((threadIdx.x & 31) == 0) sr[threadIdx.x >> 5] = v;
    __syncthreads();
    if (threadIdx.x < 32) {
        float t = sr[threadIdx.x];
        #pragma unroll
        for (int o = 16; o; o >>= 1) t += __shfl_xor_sync(0xffffffffu, t, o);
        if (threadIdx.x == 0) res = t;
    }
    __syncthreads();
    float out = res;
    __syncthreads();
    return out;
}

// -------------------- 1) spectral norm power iteration --------------------
__global__ void spectral_kernel(const float* __restrict__ Wh,
                                const float* __restrict__ u0) {
    __shared__ float su[D_DIM];
    __shared__ float sv[D_DIM];
    __shared__ float sraw[D_DIM];
    const int tid  = threadIdx.x;
    const int w    = tid >> 5;
    const int lane = tid & 31;

    float x0 = u0[tid];
    float n0 = sqrtf(block_sum1024(x0 * x0));
    su[tid] = x0 / n0;
    __syncthreads();

    for (int it = 0; it < 3; it++) {
        {   // v = W^T u
            float a = 0.f;
            const float* col = Wh + tid;
            #pragma unroll 4
            for (int i = 0; i < D_DIM; i++)
                a = fmaf(col[(size_t)i * D_DIM], su[i], a);
            float nrm = sqrtf(block_sum1024(a * a));
            sv[tid] = a / (nrm + 1e-8f);
            __syncthreads();
        }
        {   // u_raw = W v
            for (int s = 0; s < 32; s++) {
                int r = w * 32 + s;
                const float* row = Wh + (size_t)r * D_DIM;
                float a = 0.f;
                #pragma unroll 4
                for (int k = lane; k < D_DIM; k += 32)
                    a = fmaf(row[k], sv[k], a);
                #pragma unroll
                for (int o = 16; o; o >>= 1) a += __shfl_xor_sync(0xffffffffu, a, o);
                if (lane == 0) sraw[r] = a;
            }
            __syncthreads();
            float rv  = sraw[tid];
            float nrm = sqrtf(block_sum1024(rv * rv));
            su[tid] = rv / (nrm + 1e-8f);
            __syncthreads();
        }
    }
    float sg = block_sum1024(su[tid] * sraw[tid]);
    if (tid == 0) g_scale = 0.99f / (fabsf(sg) + 1e-8f);
}

// -------------------- helpers --------------------
__device__ __forceinline__ void tf32_split(float v, float& h, float& l) {
    uint32_t hb; asm("cvt.rna.tf32.f32 %0, %1;" : "=r"(hb) : "f"(v));
    float hf = __uint_as_float(hb);
    float lv = v - hf;
    uint32_t lb; asm("cvt.rna.tf32.f32 %0, %1;" : "=r"(lb) : "f"(lv));
    h = hf; l = __uint_as_float(lb);
}

__device__ __forceinline__ void bf16_split(float v, __nv_bfloat16& h, __nv_bfloat16& l) {
    h = __float2bfloat16_rn(v);
    l = __float2bfloat16_rn(v - __bfloat162float(h));
}

// bf16-unit index into g_spack for state element (d, n): hi at uoff p>>2, lo at 2+(p>>2)
__device__ __forceinline__ int spack_idx(int d, int n, int is_lo) {
    int sblk = d >> 4;
    int kk   = d & 15;
    int p    = kk >> 1;
    int j    = kk & 1;
    int tigp = p & 3;
    int uoff = (is_lo ? 2 : 0) + (p >> 2);
    return (sblk * 128 + tigp * 32 + n * 4 + uoff) * 2 + j;
}

// -------------------- 2a) split W_x once (reused by all 512 m-tiles) --------------------
__global__ void wsplit_kernel(const float* __restrict__ Wx) {
    int i = blockIdx.x * blockDim.x + threadIdx.x;
    if (i < D_DIM * D_DIM) {
        float h, l;
        tf32_split(Wx[i], h, l);
        g_WxHi[i] = h;
        g_WxLo[i] = l;
    }
}

// -------------------- 2b) prep: pack h0 into bf16 state, copy h0 to output ----------
__global__ void prep_kernel(const float* __restrict__ h0,
                            float* __restrict__ hout0) {
    int i = blockIdx.x * blockDim.x + threadIdx.x;
    if (i < B_DIM * D_DIM) {
        int b = i >> 10;
        int d = i & (D_DIM - 1);
        int g = b >> 3;
        int n = b & 7;
        float v = h0[i];
        __nv_bfloat16 hi, lo;
        bf16_split(v, hi, lo);
        __nv_bfloat16* sp = (__nv_bfloat16*)g_spack[g][0];
        sp[spack_idx(d, n, 0)] = hi;
        sp[spack_idx(d, n, 1)] = lo;
        hout0[i] = v;
    }
}

// -------------------- 3) split-tf32 tensor-core GEMM (R9, known-good 2.0ms) ----------
#define GS 36

__device__ __forceinline__ void mma_tf32(float* c, const uint32_t* a, const uint32_t* b) {
    asm volatile(
        "mma.sync.aligned.m16n8k8.row.col.f32.tf32.tf32.f32 "
        "{%0,%1,%2,%3}, {%4,%5,%6,%7}, {%8,%9}, {%0,%1,%2,%3};"
        : "+f"(c[0]), "+f"(c[1]), "+f"(c[2]), "+f"(c[3])
        : "r"(a[0]), "r"(a[1]), "r"(a[2]), "r"(a[3]), "r"(b[0]), "r"(b[1]));
}

__global__ __launch_bounds__(256, 2)
void gemm_tf32_kernel(const float* __restrict__ X,
                      float* __restrict__ C) {
    extern __shared__ float gsm[];
    float* Xh = gsm;
    float* Xl = Xh + 128 * GS;
    float* Wh = Xl + 128 * GS;
    float* Wl = Wh + 128 * GS;

    const float* __restrict__ WHi = g_WxHi;
    const float* __restrict__ WLo = g_WxLo;

    const int tid  = threadIdx.x;
    const int bn   = blockIdx.x * 128;
    const int bm   = blockIdx.y * 128;
    const int wid  = tid >> 5, lane = tid & 31;
    const int wm   = wid >> 2;
    const int wn   = wid & 3;
    const int gid  = lane >> 2, tig = lane & 3;

    float c[4][4][4];
    #pragma unroll
    for (int mt = 0; mt < 4; mt++)
        #pragma unroll
        for (int nt = 0; nt < 4; nt++)
            #pragma unroll
            for (int r = 0; r < 4; r++) c[mt][nt][r] = 0.f;

    const int sr = tid >> 3;
    const int sc = (tid & 7) * 4;

    for (int k0 = 0; k0 < D_DIM; k0 += 32) {
        __syncthreads();
        #pragma unroll
        for (int j = 0; j < 4; j++) {
            int row = sr + j * 32;
            float4 xv  = *(const float4*)&X[(size_t)(bm + row) * D_DIM + k0 + sc];
            float4 wvh = *(const float4*)&WHi[(size_t)(bn + row) * D_DIM + k0 + sc];
            float4 wvl = *(const float4*)&WLo[(size_t)(bn + row) * D_DIM + k0 + sc];
            float h, l;
            tf32_split(xv.x, h, l); Xh[row*GS+sc+0]=h; Xl[row*GS+sc+0]=l;
            tf32_split(xv.y, h, l); Xh[row*GS+sc+1]=h; Xl[row*GS+sc+1]=l;
            tf32_split(xv.z, h, l); Xh[row*GS+sc+2]=h; Xl[row*GS+sc+2]=l;
            tf32_split(xv.w, h, l); Xh[row*GS+sc+3]=h; Xl[row*GS+sc+3]=l;
            *(float4*)&Wh[row*GS+sc] = wvh;
            *(float4*)&Wl[row*GS+sc] = wvl;
        }
        __syncthreads();
        #pragma unroll
        for (int k8 = 0; k8 < 4; k8++) {
            const int kk = k8 * 8 + tig;
            uint32_t ah[4][4], al[4][4], bh[4][2], bl[4][2];
            #pragma unroll
            for (int mt = 0; mt < 4; mt++) {
                int r0 = wm * 64 + mt * 16 + gid;
                const float* p0 = &Xh[r0 * GS + kk];
                ah[mt][0] = __float_as_uint(p0[0]);
                ah[mt][1] = __float_as_uint(p0[8 * GS]);
                ah[mt][2] = __float_as_uint(p0[4]);
                ah[mt][3] = __float_as_uint(p0[8 * GS + 4]);
                const float* p1 = &Xl[r0 * GS + kk];
                al[mt][0] = __float_as_uint(p1[0]);
                al[mt][1] = __float_as_uint(p1[8 * GS]);
                al[mt][2] = __float_as_uint(p1[4]);
                al[mt][3] = __float_as_uint(p1[8 * GS + 4]);
            }
            #pragma unroll
            for (int nt = 0; nt < 4; nt++) {
                int c0n = wn * 32 + nt * 8 + gid;
                const float* p0 = &Wh[c0n * GS + kk];
                bh[nt][0] = __float_as_uint(p0[0]);
                bh[nt][1] = __float_as_uint(p0[4]);
                const float* p1 = &Wl[c0n * GS + kk];
                bl[nt][0] = __float_as_uint(p1[0]);
                bl[nt][1] = __float_as_uint(p1[4]);
            }
            #pragma unroll
            for (int mt = 0; mt < 4; mt++)
                #pragma unroll
                for (int nt = 0; nt < 4; nt++) {
                    mma_tf32(c[mt][nt], ah[mt], bh[nt]);
                    mma_tf32(c[mt][nt], ah[mt], bl[nt]);
                    mma_tf32(c[mt][nt], al[mt], bh[nt]);
                }
        }
    }
    #pragma unroll
    for (int mt = 0; mt < 4; mt++) {
        int row = bm + wm * 64 + mt * 16 + gid;
        #pragma unroll
        for (int nt = 0; nt < 4; nt++) {
            int col = bn + wn * 32 + nt * 8 + 2 * tig;
            *(float2*)&C[(size_t)row * D_DIM + col]       = make_float2(c[mt][nt][0], c[mt][nt][1]);
            *(float2*)&C[(size_t)(row + 8) * D_DIM + col] = make_float2(c[mt][nt][2], c[mt][nt][3]);
        }
    }
}

// -------------------- 4) persistent scan kernel (v5: bf16-split mma recurrence) ------
// Group g (32 blocks) owns batches [8g,8g+8). Block owns 32 e's (2 m16 tiles).
// Per step: dot[32,8] = W[32,1024] @ h[1024,8] via mma.m16n8k16.bf16, 2-term bf16
// split of BOTH W and h (3 products). W fragments preloaded into 128 registers.
// h state packed in B-fragment layout -> 1 LDG.128 per warp per k16-step.
// 8 warps cover K (128 each); cross-warp reduce of 8 partials in smem.
__device__ __forceinline__ void mma_bf16(float* c, const uint32_t* a, uint32_t b0, uint32_t b1) {
    asm volatile(
        "mma.sync.aligned.m16n8k16.row.col.f32.bf16.bf16.f32 "
        "{%0,%1,%2,%3}, {%4,%5,%6,%7}, {%8,%9}, {%0,%1,%2,%3};"
        : "+f"(c[0]), "+f"(c[1]), "+f"(c[2]), "+f"(c[3])
        : "r"(a[0]), "r"(a[1]), "r"(a[2]), "r"(a[3]), "r"(b0), "r"(b1));
}

__device__ __forceinline__ uint32_t pack_bf16x2(float f0, float f1) {
    __nv_bfloat162 t;
    t.x = __float2bfloat16_rn(f0);
    t.y = __float2bfloat16_rn(f1);
    return *(uint32_t*)&t;
}

__global__ __launch_bounds__(256, 1)
void scan_kernel(const float* __restrict__ Whmat,
                 float* __restrict__ wx_out,        // [T][B][D]: in = Wx, overwritten with out
                 float* __restrict__ hout,          // [T+1][B][D]
                 const float* __restrict__ bvec,
                 const float* __restrict__ bgvec,
                 int T) {
    __shared__ __align__(16) float red[10240];

    const int tid  = threadIdx.x;
    const int g    = blockIdx.x >> 5;     // group 0..3
    const int r    = blockIdx.x & 31;     // rank in group
    const int e0   = r * 32;
    const int b0   = g * BSUB;
    const int bar  = g * 32;

    const int w    = tid >> 5;            // warp 0..7, covers k in [w*128, w*128+128)
    const int lane = tid & 31;
    const int gid  = lane >> 2;           // 0..7
    const int tig  = lane & 3;            // 0..3

    // ---- preload W A-fragments into registers (hi/lo bf16 split, scaled) ----
    const float s = g_scale;
    uint32_t Ah[2][8][4], Al[2][8][4];
    #pragma unroll
    for (int mt = 0; mt < 2; mt++) {
        #pragma unroll
        for (int ks = 0; ks < 8; ks++) {
            const int k0 = w * 128 + ks * 16 + 2 * tig;
            const int r0 = e0 + mt * 16 + gid;
            // a0:(r0,k0,k0+1) a1:(r0+8,k0..) a2:(r0,k0+8..) a3:(r0+8,k0+8..)
            #pragma unroll
            for (int i = 0; i < 4; i++) {
                const int rr = r0 + ((i & 1) ? 8 : 0);
                const int kk = k0 + ((i & 2) ? 8 : 0);
                float f0 = Whmat[(size_t)rr * D_DIM + kk]     * s;
                float f1 = Whmat[(size_t)rr * D_DIM + kk + 1] * s;
                __nv_bfloat16 h0b, l0b, h1b, l1b;
                bf16_split(f0, h0b, l0b);
                bf16_split(f1, h1b, l1b);
                __nv_bfloat162 th; th.x = h0b; th.y = h1b;
                __nv_bfloat162 tl; tl.x = l0b; tl.y = l1b;
                Ah[mt][ks][i] = *(uint32_t*)&th;
                Al[mt][ks][i] = *(uint32_t*)&tl;
            }
        }
    }

    // epilogue mapping: thread -> (e = tid&31, b = tid>>5)
    const int eL = tid & 31;
    const int bO = tid >> 5;
    const float bb  = bvec[e0 + eL];
    const float bgg = bgvec[e0 + eL];
    const int oaddr = (eL * 8 + bO) * 40 + (eL & 3) * 8;   // reduce base (slots 0..7)
    // state publish indices (bf16 units)
    const int pub_hi = spack_idx(e0 + eL, bO, 0);
    const int pub_lo = spack_idx(e0 + eL, bO, 1);

    __syncthreads();

    unsigned gen = g_genv[bar];
    int par = 0;

    for (int t = 0; t < T; t++) {
        // prefetch Wx element (L2 latency overlaps mma loop)
        const size_t gidx = ((size_t)t * B_DIM + (b0 + bO)) * D_DIM + (e0 + eL);
        const float wxv = __ldcg(&wx_out[gidx]);

        float c0[4] = {0.f, 0.f, 0.f, 0.f};
        float c1[4] = {0.f, 0.f, 0.f, 0.f};

        const uint4* bp = (const uint4*)g_spack[g][par];
        #pragma unroll
        for (int ks = 0; ks < 8; ks++) {
            uint4 v = __ldcg(&bp[(w * 8 + ks) * 32 + tig * 8 + gid]);
            // v = (bhi0, bhi1, blo0, blo1)
            mma_bf16(c0, Ah[0][ks], v.x, v.y);
            mma_bf16(c0, Ah[0][ks], v.z, v.w);
            mma_bf16(c0, Al[0][ks], v.x, v.y);
            mma_bf16(c1, Ah[1][ks], v.x, v.y);
            mma_bf16(c1, Ah[1][ks], v.z, v.w);
            mma_bf16(c1, Al[1][ks], v.x, v.y);
        }

        // ---- partials -> smem: value (e_loc, col) at (e_loc*8+col)*40 + (e_loc&3)*8 + w
        {
            const int rot = (gid & 3) * 8;
            int ebase = e0 ? 0 : 0; (void)ebase;
            // m-tile 0: rows gid, gid+8
            int a0 = (gid * 8 + 2 * tig) * 40 + rot + w;
            red[a0]      = c0[0];
            red[a0 + 40] = c0[1];
            int a2 = ((gid + 8) * 8 + 2 * tig) * 40 + rot + w;
            red[a2]      = c0[2];
            red[a2 + 40] = c0[3];
            // m-tile 1: rows 16+gid, 24+gid
            int a4 = ((16 + gid) * 8 + 2 * tig) * 40 + rot + w;
            red[a4]      = c1[0];
            red[a4 + 40] = c1[1];
            int a6 = ((24 + gid) * 8 + 2 * tig) * 40 + rot + w;
            red[a6]      = c1[2];
            red[a6 + 40] = c1[3];
        }
        __syncthreads();

        // ---- reduce 8 partials (2x LDS.128) + epilogue ----
        {
            float4 v0 = *(const float4*)&red[oaddr];
            float4 v1 = *(const float4*)&red[oaddr + 4];
            const float dot = ((v0.x + v0.y) + (v0.z + v0.w))
                            + ((v1.x + v1.y) + (v1.z + v1.w));
            const float raw = wxv + dot + bb;
            const float ex  = __expf(2.f * raw);
            const float hn  = 1.f - 2.f / (ex + 1.f);           // tanh(raw)
            const float gg  = wxv + hn + bgg;
            const float ov  = hn * gg / (1.f + __expf(-gg));    // hn * silu(gg)
            wx_out[gidx] = ov;
            hout[((size_t)(t + 1) * B_DIM + (b0 + bO)) * D_DIM + (e0 + eL)] = hn;
            // publish next state (bf16 hi/lo, B-fragment layout)
            __nv_bfloat16 hi, lo;
            bf16_split(hn, hi, lo);
            __nv_bfloat16* sp = (__nv_bfloat16*)g_spack[g][par ^ 1];
            sp[pub_hi] = hi;
            sp[pub_lo] = lo;
        }
        __syncthreads();

        // ---- per-group barrier ----
        if (tid == 0) {
            __threadfence();
            if (atomicAdd(&g_cnt[bar], 1u) == GSZ - 1) {
                atomicExch(&g_cnt[bar], 0u);
                __threadfence();
                g_genv[bar] = gen + 1;
            } else {
                while (g_genv[bar] == gen) { }
            }
            gen = gen + 1;
        }
        __syncthreads();
        par ^= 1;
    }
}

// -------------------- launcher --------------------
extern "C" void kernel_launch(void* const* d_in, const int* in_sizes, int n_in,
                              void* d_out, int out_size) {
    const float* x      = (const float*)d_in[0];
    // d_in[1] = z (unused, gate_mode 0)
    const float* h0     = (const float*)d_in[2];
    const float* W_x    = (const float*)d_in[3];
    const float* W_h    = (const float*)d_in[4];
    const float* bvec   = (const float*)d_in[5];
    const float* bgvec  = (const float*)d_in[6];
    const float* u0     = (const float*)d_in[7];

    const int T = in_sizes[0] / (B_DIM * D_DIM);   // 2048
    const int M = T * B_DIM;                       // 65536

    float* out_region = (float*)d_out;                               // [T][B][D]
    float* h_region   = (float*)d_out + (size_t)T * B_DIM * D_DIM;   // [T+1][B][D]

    const size_t gemm_smem = 4 * 128 * GS * sizeof(float);           // 73728 B

    static bool attrs_set = false;
    if (!attrs_set) {
        cudaFuncSetAttribute(gemm_tf32_kernel,
                             cudaFuncAttributeMaxDynamicSharedMemorySize, (int)gemm_smem);
        attrs_set = true;
    }

    wsplit_kernel<<<(D_DIM * D_DIM + 255) / 256, 256>>>(W_x);
    spectral_kernel<<<1, 1024>>>(W_h, u0);
    prep_kernel<<<(B_DIM * D_DIM + 255) / 256, 256>>>(h0, h_region);

    {
        dim3 grid(D_DIM / 128, M / 128);
        gemm_tf32_kernel<<<grid, 256, gemm_smem>>>(x, out_region);
    }

    scan_kernel<<<NBLK, 256>>>(W_h, out_region, h_region, bvec, bgvec, T);
}